// round 16
// baseline (speedup 1.0000x reference)
#include <cuda_runtime.h>
#include <cuda_bf16.h>
#include <cstdint>

#define TT   2048
#define DD   64
#define CH   64
#define NC   (TT/CH)    // 32 chunks
#define BH   64         // B*H
#define PIT  72         // smem pitch in bf16 elements (144B rows, ldmatrix conflict-free)
#define TILE_B (DD*PIT*2)  // 9216 bytes per 64x64 bf16 tile

// Exclusive-prefix KV states, fp32: 32 MB
__device__ float g_state[(size_t)BH * NC * DD * DD];

// ---------------------------------------------------------------------------
// helpers
// ---------------------------------------------------------------------------
__device__ __forceinline__ uint32_t smem_u32(const void* p) {
    uint32_t a;
    asm("{ .reg .u64 t; cvta.to.shared.u64 t, %1; cvt.u32.u64 %0, t; }" : "=r"(a) : "l"(p));
    return a;
}
__device__ __forceinline__ void ldsm4(uint32_t addr, uint32_t r[4]) {
    asm volatile("ldmatrix.sync.aligned.m8n8.x4.shared.b16 {%0,%1,%2,%3}, [%4];"
                 : "=r"(r[0]), "=r"(r[1]), "=r"(r[2]), "=r"(r[3]) : "r"(addr));
}
__device__ __forceinline__ void ldsm4t(uint32_t addr, uint32_t r[4]) {
    asm volatile("ldmatrix.sync.aligned.m8n8.x4.trans.shared.b16 {%0,%1,%2,%3}, [%4];"
                 : "=r"(r[0]), "=r"(r[1]), "=r"(r[2]), "=r"(r[3]) : "r"(addr));
}
__device__ __forceinline__ void mma16816(float c[4], const uint32_t a[4], uint32_t b0, uint32_t b1) {
    asm volatile(
        "mma.sync.aligned.m16n8k16.row.col.f32.bf16.bf16.f32 "
        "{%0,%1,%2,%3}, {%4,%5,%6,%7}, {%8,%9}, {%0,%1,%2,%3};"
        : "+f"(c[0]), "+f"(c[1]), "+f"(c[2]), "+f"(c[3])
        : "r"(a[0]), "r"(a[1]), "r"(a[2]), "r"(a[3]), "r"(b0), "r"(b1));
}
__device__ __forceinline__ uint32_t cvt_bf2(float hi, float lo) {
    uint32_t d;
    asm("cvt.rn.bf16x2.f32 %0, %1, %2;" : "=r"(d) : "f"(hi), "f"(lo));
    return d;
}
__device__ __forceinline__ void split2(float x, float y, uint32_t& h, uint32_t& l) {
    h = cvt_bf2(y, x);
    float rx = x - __uint_as_float(h << 16);
    float ry = y - __uint_as_float(h & 0xFFFF0000u);
    l = cvt_bf2(ry, rx);
}
__device__ __forceinline__ void split4(float4 f, uint2& hi, uint2& lo) {
    split2(f.x, f.y, hi.x, lo.x);
    split2(f.z, f.w, hi.y, lo.y);
}

// ---------------------------------------------------------------------------
// Kernel 1: KV_c = K_c^T V_c — 8-warp (R15-exact)
// ---------------------------------------------------------------------------
#define K1_KH 0
#define K1_KL (1*TILE_B)
#define K1_VH (2*TILE_B)
#define K1_VL (3*TILE_B)
#define K1_SMEM (4*TILE_B)

__global__ __launch_bounds__(256) void kv_kernel(const float* __restrict__ kg,
                                                 const float* __restrict__ vg) {
    extern __shared__ char sm[];
    const uint32_t sb = smem_u32(sm);
    const int tid = threadIdx.x, w = tid >> 5, l = tid & 31;
    const int c = blockIdx.x, bh = blockIdx.y;

    const float* kp = kg + ((size_t)bh * TT + (size_t)c * CH) * DD;
    const float* vp = vg + ((size_t)bh * TT + (size_t)c * CH) * DD;

#pragma unroll
    for (int it = 0; it < 4; it++) {
        int idx = tid + it * 256;
        int j = idx >> 4, d0 = (idx & 15) * 4;
        uint2 hi, lo;
        split4(*(const float4*)(kp + (size_t)j * DD + d0), hi, lo);
        *(uint2*)(sm + K1_KH + (j * PIT + d0) * 2) = hi;
        *(uint2*)(sm + K1_KL + (j * PIT + d0) * 2) = lo;
        split4(*(const float4*)(vp + (size_t)j * DD + d0), hi, lo);
        *(uint2*)(sm + K1_VH + (j * PIT + d0) * 2) = hi;
        *(uint2*)(sm + K1_VL + (j * PIT + d0) * 2) = lo;
    }
    __syncthreads();

    const int m0 = (w & 3) * 16, n0 = (w >> 2) * 32;
    const uint32_t aOff = (((l & 7) + ((l >> 4) & 1) * 8) * PIT + m0 + (l & 8)) * 2;
    const uint32_t bOff = (((l & 7) + (l & 8)) * PIT + n0 + ((l >> 4) & 1) * 8) * 2;

    float acc[4][4] = {};
    const uint32_t aSel[3] = {K1_KH, K1_KH, K1_KL};
    const uint32_t bSel[3] = {K1_VH, K1_VL, K1_VH};
#pragma unroll
    for (int p = 0; p < 3; p++) {
        const uint32_t aB = sb + aSel[p] + aOff, bB = sb + bSel[p] + bOff;
#pragma unroll
        for (int ks = 0; ks < 4; ks++) {
            const uint32_t ko = ks * 16 * PIT * 2;
            uint32_t a0[4], b0[4], b1[4];
            ldsm4t(aB + ko, a0);
            ldsm4t(bB + ko, b0);
            ldsm4t(bB + ko + 32, b1);
            mma16816(acc[0], a0, b0[0], b0[1]);
            mma16816(acc[1], a0, b0[2], b0[3]);
            mma16816(acc[2], a0, b1[0], b1[1]);
            mma16816(acc[3], a0, b1[2], b1[3]);
        }
    }

    float* outp = g_state + ((size_t)(bh * NC + c)) * (DD * DD);
#pragma unroll
    for (int ni = 0; ni < 4; ni++)
#pragma unroll
        for (int half = 0; half < 2; half++) {
            int d = m0 + (l >> 2) + half * 8;
            int e = n0 + ni * 8 + 2 * (l & 3);
            *(float2*)(outp + (size_t)d * DD + e) =
                make_float2(acc[ni][2 * half], acc[ni][2 * half + 1]);
        }
}

// ---------------------------------------------------------------------------
// Kernel 2: exclusive prefix (unchanged)
// ---------------------------------------------------------------------------
__global__ __launch_bounds__(256) void prefix_kernel() {
    const int e = blockIdx.x * 256 + threadIdx.x;
    const int bh = blockIdx.y;
    size_t base = (size_t)bh * NC * (DD * DD) + e;
    float run = 0.f;
#pragma unroll
    for (int c = 0; c < NC; c++) {
        float t = g_state[base + (size_t)c * (DD * DD)];
        g_state[base + (size_t)c * (DD * DD)] = run;
        run += t;
    }
}

// ---------------------------------------------------------------------------
// Kernel 3: 8-warp out, P overlaid into K tiles after P-pass (8 smem tiles).
// ---------------------------------------------------------------------------
#define K3_QH 0
#define K3_QL (1*TILE_B)
#define K3_KPH (2*TILE_B)   // K during P-pass; P planes afterwards
#define K3_KPL (3*TILE_B)
#define K3_VH (4*TILE_B)
#define K3_VL (5*TILE_B)
#define K3_SH (6*TILE_B)
#define K3_SL (7*TILE_B)
#define K3_SMEM (8*TILE_B)   // 73728 B -> 3 CTAs/SM

__global__ __launch_bounds__(256) void out_kernel(const float* __restrict__ qg,
                                                  const float* __restrict__ kg,
                                                  const float* __restrict__ vg,
                                                  float* __restrict__ og) {
    extern __shared__ char sm[];
    const uint32_t sb = smem_u32(sm);
    const int tid = threadIdx.x, w = tid >> 5, l = tid & 31;
    const int c = blockIdx.x, bh = blockIdx.y;

    const float* qp = qg + ((size_t)bh * TT + (size_t)c * CH) * DD;
    const float* kp = kg + ((size_t)bh * TT + (size_t)c * CH) * DD;
    const float* vp = vg + ((size_t)bh * TT + (size_t)c * CH) * DD;
    const float* sp = g_state + ((size_t)(bh * NC + c)) * (DD * DD);

#pragma unroll
    for (int it = 0; it < 4; it++) {
        int idx = tid + it * 256;
        int r_ = idx >> 4, d0 = (idx & 15) * 4;
        const uint32_t so = (r_ * PIT + d0) * 2;
        uint2 hi, lo;
        split4(*(const float4*)(qp + (size_t)r_ * DD + d0), hi, lo);
        *(uint2*)(sm + K3_QH + so) = hi;   *(uint2*)(sm + K3_QL + so) = lo;
        split4(*(const float4*)(kp + (size_t)r_ * DD + d0), hi, lo);
        *(uint2*)(sm + K3_KPH + so) = hi;  *(uint2*)(sm + K3_KPL + so) = lo;
        split4(*(const float4*)(vp + (size_t)r_ * DD + d0), hi, lo);
        *(uint2*)(sm + K3_VH + so) = hi;   *(uint2*)(sm + K3_VL + so) = lo;
        split4(*(const float4*)(sp + (size_t)r_ * DD + d0), hi, lo);
        *(uint2*)(sm + K3_SH + so) = hi;   *(uint2*)(sm + K3_SL + so) = lo;
    }
    __syncthreads();

    const int r = w & 3;       // row block: rows 16r..16r+15
    const int h = w >> 2;      // n-half: cols 32h..32h+31
    const int m0 = r * 16;
    const int gid = l >> 2, tig = l & 3;
    const int i0 = m0 + gid;
    const uint32_t aOffN = ((m0 + (l & 15)) * PIT + ((l >> 4) << 3)) * 2;
    const uint32_t bOffN = (((l & 7) + ((l & 16) >> 1)) * PIT + ((l >> 3) & 1) * 8) * 2;
    const uint32_t bOffT = (((l & 7) + (l & 8)) * PIT + ((l >> 4) & 1) * 8) * 2;

    // ---- P quarter: rows 16r x cols [32h, 32h+32), causal nb <= r ----
    float accP[4][4] = {};
    {
        const uint32_t aS[3] = {K3_QH, K3_QH, K3_QL};
        const uint32_t bS[3] = {K3_KPH, K3_KPL, K3_KPH};
#pragma unroll
        for (int p = 0; p < 3; p++) {
            const uint32_t aB = sb + aS[p] + aOffN, bB = sb + bS[p] + bOffN;
#pragma unroll
            for (int ks = 0; ks < 4; ks++) {
                uint32_t a[4];
                ldsm4(aB + ks * 32, a);
#pragma unroll
                for (int nbL = 0; nbL < 2; nbL++) {
                    const int nb = 2 * h + nbL;
                    if (nb <= r) {
                        uint32_t b[4];
                        ldsm4(bB + nb * 16 * PIT * 2 + ks * 32, b);
                        mma16816(accP[2 * nbL],     a, b[0], b[1]);
                        mma16816(accP[2 * nbL + 1], a, b[2], b[3]);
                    }
                }
            }
        }
    }

    // all warps done reading K before P overwrites the K tiles
    __syncthreads();

    // ---- mask + split + store P quarter into the (dead) K tiles ----
#pragma unroll
    for (int nbL = 0; nbL < 2; nbL++) {
        const int nb = 2 * h + nbL;
        if (nb <= r) {
#pragma unroll
            for (int s2 = 0; s2 < 2; s2++) {
                const int j0 = 16 * nb + 8 * s2 + 2 * tig;
                float c0 = (j0     <= i0)     ? accP[2 * nbL + s2][0] : 0.f;
                float c1 = (j0 + 1 <= i0)     ? accP[2 * nbL + s2][1] : 0.f;
                float c2 = (j0     <= i0 + 8) ? accP[2 * nbL + s2][2] : 0.f;
                float c3 = (j0 + 1 <= i0 + 8) ? accP[2 * nbL + s2][3] : 0.f;
                uint32_t hw, lw;
                split2(c0, c1, hw, lw);
                *(uint32_t*)(sm + K3_KPH + (i0 * PIT + j0) * 2) = hw;
                *(uint32_t*)(sm + K3_KPL + (i0 * PIT + j0) * 2) = lw;
                split2(c2, c3, hw, lw);
                *(uint32_t*)(sm + K3_KPH + ((i0 + 8) * PIT + j0) * 2) = hw;
                *(uint32_t*)(sm + K3_KPL + ((i0 + 8) * PIT + j0) * 2) = lw;
            }
        }
    }
    __syncthreads();

    // ---- O1 = Q @ S for e-half h ----
    float accO[4][4] = {};
    {
        const uint32_t aS[3] = {K3_QH, K3_QH, K3_QL};
        const uint32_t bS[3] = {K3_SH, K3_SL, K3_SH};
#pragma unroll
        for (int p = 0; p < 3; p++) {
            const uint32_t aB = sb + aS[p] + aOffN, bB = sb + bS[p] + bOffT;
#pragma unroll
            for (int ks = 0; ks < 4; ks++) {
                uint32_t a[4];
                ldsm4(aB + ks * 32, a);
#pragma unroll
                for (int nbL = 0; nbL < 2; nbL++) {
                    const int nbE = 2 * h + nbL;
                    uint32_t b[4];
                    ldsm4t(bB + ks * 16 * PIT * 2 + nbE * 32, b);
                    mma16816(accO[2 * nbL],     a, b[0], b[1]);
                    mma16816(accO[2 * nbL + 1], a, b[2], b[3]);
                }
            }
        }
    }

    // ---- O2 += P @ V (A = P from K slots, kb <= r; B = V^T trans) ----
    {
#pragma unroll
        for (int p = 0; p < 3; p++) {
            const uint32_t aB = sb + (p == 2 ? K3_KPL : K3_KPH) + aOffN;
            const uint32_t bB = sb + (p == 1 ? K3_VL : K3_VH) + bOffT;
#pragma unroll
            for (int kb = 0; kb < 4; kb++)
                if (kb <= r) {
                    uint32_t a[4];
                    ldsm4(aB + kb * 32, a);
#pragma unroll
                    for (int nbL = 0; nbL < 2; nbL++) {
                        const int nbE = 2 * h + nbL;
                        uint32_t b[4];
                        ldsm4t(bB + kb * 16 * PIT * 2 + nbE * 32, b);
                        mma16816(accO[2 * nbL],     a, b[0], b[1]);
                        mma16816(accO[2 * nbL + 1], a, b[2], b[3]);
                    }
                }
        }
    }

    // ---- store O ----
    float* op = og + ((size_t)bh * TT + (size_t)c * CH) * DD;
#pragma unroll
    for (int nb8 = 0; nb8 < 4; nb8++) {
        const int e = 32 * h + 8 * nb8 + 2 * tig;
        *(float2*)(op + (size_t)i0 * DD + e)       = make_float2(accO[nb8][0], accO[nb8][1]);
        *(float2*)(op + (size_t)(i0 + 8) * DD + e) = make_float2(accO[nb8][2], accO[nb8][3]);
    }
}

// ---------------------------------------------------------------------------
extern "C" void kernel_launch(void* const* d_in, const int* in_sizes, int n_in,
                              void* d_out, int out_size) {
    const float* q = (const float*)d_in[0];
    const float* k = (const float*)d_in[1];
    const float* v = (const float*)d_in[2];
    float* o = (float*)d_out;

    cudaFuncSetAttribute(kv_kernel, cudaFuncAttributeMaxDynamicSharedMemorySize, K1_SMEM);
    cudaFuncSetAttribute(out_kernel, cudaFuncAttributeMaxDynamicSharedMemorySize, K3_SMEM);

    dim3 grid(NC, BH);
    kv_kernel<<<grid, 256, K1_SMEM>>>(k, v);
    prefix_kernel<<<dim3((DD * DD) / 256, BH), 256>>>();
    out_kernel<<<grid, 256, K3_SMEM>>>(q, k, v, o);
}

// round 17
// speedup vs baseline: 1.0861x; 1.0861x over previous
#include <cuda_runtime.h>
#include <cuda_bf16.h>
#include <cstdint>

#define TT   2048
#define DD   64
#define CH   64
#define NC   (TT/CH)    // 32 chunks
#define BH   64         // B*H
#define PIT  72         // smem pitch in bf16 elements (144B rows, ldmatrix conflict-free)
#define TILE_B (DD*PIT*2)  // 9216 bytes per 64x64 bf16 tile

// Exclusive-prefix KV states, fp32: 32 MB
__device__ float g_state[(size_t)BH * NC * DD * DD];

// ---------------------------------------------------------------------------
// helpers
// ---------------------------------------------------------------------------
__device__ __forceinline__ uint32_t smem_u32(const void* p) {
    uint32_t a;
    asm("{ .reg .u64 t; cvta.to.shared.u64 t, %1; cvt.u32.u64 %0, t; }" : "=r"(a) : "l"(p));
    return a;
}
__device__ __forceinline__ void ldsm4(uint32_t addr, uint32_t r[4]) {
    asm volatile("ldmatrix.sync.aligned.m8n8.x4.shared.b16 {%0,%1,%2,%3}, [%4];"
                 : "=r"(r[0]), "=r"(r[1]), "=r"(r[2]), "=r"(r[3]) : "r"(addr));
}
__device__ __forceinline__ void ldsm4t(uint32_t addr, uint32_t r[4]) {
    asm volatile("ldmatrix.sync.aligned.m8n8.x4.trans.shared.b16 {%0,%1,%2,%3}, [%4];"
                 : "=r"(r[0]), "=r"(r[1]), "=r"(r[2]), "=r"(r[3]) : "r"(addr));
}
__device__ __forceinline__ void mma16816(float c[4], const uint32_t a[4], uint32_t b0, uint32_t b1) {
    asm volatile(
        "mma.sync.aligned.m16n8k16.row.col.f32.bf16.bf16.f32 "
        "{%0,%1,%2,%3}, {%4,%5,%6,%7}, {%8,%9}, {%0,%1,%2,%3};"
        : "+f"(c[0]), "+f"(c[1]), "+f"(c[2]), "+f"(c[3])
        : "r"(a[0]), "r"(a[1]), "r"(a[2]), "r"(a[3]), "r"(b0), "r"(b1));
}
__device__ __forceinline__ uint32_t cvt_bf2(float hi, float lo) {
    uint32_t d;
    asm("cvt.rn.bf16x2.f32 %0, %1, %2;" : "=r"(d) : "f"(hi), "f"(lo));
    return d;
}
__device__ __forceinline__ void split2(float x, float y, uint32_t& h, uint32_t& l) {
    h = cvt_bf2(y, x);
    float rx = x - __uint_as_float(h << 16);
    float ry = y - __uint_as_float(h & 0xFFFF0000u);
    l = cvt_bf2(ry, rx);
}
__device__ __forceinline__ void split4(float4 f, uint2& hi, uint2& lo) {
    split2(f.x, f.y, hi.x, lo.x);
    split2(f.z, f.w, hi.y, lo.y);
}

// ---------------------------------------------------------------------------
// Kernel 1: KV_c = K_c^T V_c — 8-warp, fused 3-pass (single fragment load).
// ---------------------------------------------------------------------------
#define K1_KH 0
#define K1_KL (1*TILE_B)
#define K1_VH (2*TILE_B)
#define K1_VL (3*TILE_B)
#define K1_SMEM (4*TILE_B)

__global__ __launch_bounds__(256) void kv_kernel(const float* __restrict__ kg,
                                                 const float* __restrict__ vg) {
    extern __shared__ char sm[];
    const uint32_t sb = smem_u32(sm);
    const int tid = threadIdx.x, w = tid >> 5, l = tid & 31;
    const int c = blockIdx.x, bh = blockIdx.y;

    const float* kp = kg + ((size_t)bh * TT + (size_t)c * CH) * DD;
    const float* vp = vg + ((size_t)bh * TT + (size_t)c * CH) * DD;

#pragma unroll
    for (int it = 0; it < 4; it++) {
        int idx = tid + it * 256;
        int j = idx >> 4, d0 = (idx & 15) * 4;
        uint2 hi, lo;
        split4(*(const float4*)(kp + (size_t)j * DD + d0), hi, lo);
        *(uint2*)(sm + K1_KH + (j * PIT + d0) * 2) = hi;
        *(uint2*)(sm + K1_KL + (j * PIT + d0) * 2) = lo;
        split4(*(const float4*)(vp + (size_t)j * DD + d0), hi, lo);
        *(uint2*)(sm + K1_VH + (j * PIT + d0) * 2) = hi;
        *(uint2*)(sm + K1_VL + (j * PIT + d0) * 2) = lo;
    }
    __syncthreads();

    const int m0 = (w & 3) * 16, n0 = (w >> 2) * 32;
    const uint32_t aOff = (((l & 7) + ((l >> 4) & 1) * 8) * PIT + m0 + (l & 8)) * 2;
    const uint32_t bOff = (((l & 7) + (l & 8)) * PIT + n0 + ((l >> 4) & 1) * 8) * 2;

    const uint32_t aHB = sb + K1_KH + aOff, aLB = sb + K1_KL + aOff;
    const uint32_t bHB = sb + K1_VH + bOff, bLB = sb + K1_VL + bOff;

    float acc[4][4] = {};
#pragma unroll
    for (int ks = 0; ks < 4; ks++) {
        const uint32_t ko = ks * 16 * PIT * 2;
        uint32_t aH[4], aL[4], bH0[4], bH1[4], bL0[4], bL1[4];
        ldsm4t(aHB + ko, aH);
        ldsm4t(aLB + ko, aL);
        ldsm4t(bHB + ko, bH0);
        ldsm4t(bHB + ko + 32, bH1);
        ldsm4t(bLB + ko, bL0);
        ldsm4t(bLB + ko + 32, bL1);
        // hi*hi
        mma16816(acc[0], aH, bH0[0], bH0[1]); mma16816(acc[1], aH, bH0[2], bH0[3]);
        mma16816(acc[2], aH, bH1[0], bH1[1]); mma16816(acc[3], aH, bH1[2], bH1[3]);
        // hi*lo
        mma16816(acc[0], aH, bL0[0], bL0[1]); mma16816(acc[1], aH, bL0[2], bL0[3]);
        mma16816(acc[2], aH, bL1[0], bL1[1]); mma16816(acc[3], aH, bL1[2], bL1[3]);
        // lo*hi
        mma16816(acc[0], aL, bH0[0], bH0[1]); mma16816(acc[1], aL, bH0[2], bH0[3]);
        mma16816(acc[2], aL, bH1[0], bH1[1]); mma16816(acc[3], aL, bH1[2], bH1[3]);
    }

    float* outp = g_state + ((size_t)(bh * NC + c)) * (DD * DD);
#pragma unroll
    for (int ni = 0; ni < 4; ni++)
#pragma unroll
        for (int half = 0; half < 2; half++) {
            int d = m0 + (l >> 2) + half * 8;
            int e = n0 + ni * 8 + 2 * (l & 3);
            *(float2*)(outp + (size_t)d * DD + e) =
                make_float2(acc[ni][2 * half], acc[ni][2 * half + 1]);
        }
}

// ---------------------------------------------------------------------------
// Kernel 2: exclusive prefix (unchanged)
// ---------------------------------------------------------------------------
__global__ __launch_bounds__(256) void prefix_kernel() {
    const int e = blockIdx.x * 256 + threadIdx.x;
    const int bh = blockIdx.y;
    size_t base = (size_t)bh * NC * (DD * DD) + e;
    float run = 0.f;
#pragma unroll
    for (int c = 0; c < NC; c++) {
        float t = g_state[base + (size_t)c * (DD * DD)];
        g_state[base + (size_t)c * (DD * DD)] = run;
        run += t;
    }
}

// ---------------------------------------------------------------------------
// Kernel 3: 8-warp out (R14 structure: dedicated P tiles), fused 3-pass loads.
// ---------------------------------------------------------------------------
#define K3_QH 0
#define K3_QL (1*TILE_B)
#define K3_KH (2*TILE_B)
#define K3_KL (3*TILE_B)
#define K3_VH (4*TILE_B)
#define K3_VL (5*TILE_B)
#define K3_SH (6*TILE_B)
#define K3_SL (7*TILE_B)
#define K3_PH (8*TILE_B)
#define K3_PL (9*TILE_B)
#define K3_SMEM (10*TILE_B)   // 92160 B

__global__ __launch_bounds__(256) void out_kernel(const float* __restrict__ qg,
                                                  const float* __restrict__ kg,
                                                  const float* __restrict__ vg,
                                                  float* __restrict__ og) {
    extern __shared__ char sm[];
    const uint32_t sb = smem_u32(sm);
    const int tid = threadIdx.x, w = tid >> 5, l = tid & 31;
    const int c = blockIdx.x, bh = blockIdx.y;

    const float* qp = qg + ((size_t)bh * TT + (size_t)c * CH) * DD;
    const float* kp = kg + ((size_t)bh * TT + (size_t)c * CH) * DD;
    const float* vp = vg + ((size_t)bh * TT + (size_t)c * CH) * DD;
    const float* sp = g_state + ((size_t)(bh * NC + c)) * (DD * DD);

#pragma unroll
    for (int it = 0; it < 4; it++) {
        int idx = tid + it * 256;
        int r_ = idx >> 4, d0 = (idx & 15) * 4;
        const uint32_t so = (r_ * PIT + d0) * 2;
        uint2 hi, lo;
        split4(*(const float4*)(qp + (size_t)r_ * DD + d0), hi, lo);
        *(uint2*)(sm + K3_QH + so) = hi;  *(uint2*)(sm + K3_QL + so) = lo;
        split4(*(const float4*)(kp + (size_t)r_ * DD + d0), hi, lo);
        *(uint2*)(sm + K3_KH + so) = hi;  *(uint2*)(sm + K3_KL + so) = lo;
        split4(*(const float4*)(vp + (size_t)r_ * DD + d0), hi, lo);
        *(uint2*)(sm + K3_VH + so) = hi;  *(uint2*)(sm + K3_VL + so) = lo;
        split4(*(const float4*)(sp + (size_t)r_ * DD + d0), hi, lo);
        *(uint2*)(sm + K3_SH + so) = hi;  *(uint2*)(sm + K3_SL + so) = lo;
    }
    __syncthreads();

    const int r = w & 3;       // row block: rows 16r..16r+15
    const int h = w >> 2;      // n-half: cols 32h..32h+31
    const int m0 = r * 16;
    const int gid = l >> 2, tig = l & 3;
    const int i0 = m0 + gid;
    const uint32_t aOffN = ((m0 + (l & 15)) * PIT + ((l >> 4) << 3)) * 2;
    const uint32_t bOffN = (((l & 7) + ((l & 16) >> 1)) * PIT + ((l >> 3) & 1) * 8) * 2;
    const uint32_t bOffT = (((l & 7) + (l & 8)) * PIT + ((l >> 4) & 1) * 8) * 2;

    // ---- P quarter (fused): rows 16r x cols [32h, 32h+32), causal nb <= r ----
    float accP[4][4] = {};
#pragma unroll
    for (int ks = 0; ks < 4; ks++) {
        uint32_t qH[4], qL[4];
        ldsm4(sb + K3_QH + aOffN + ks * 32, qH);
        ldsm4(sb + K3_QL + aOffN + ks * 32, qL);
#pragma unroll
        for (int nbL = 0; nbL < 2; nbL++) {
            const int nb = 2 * h + nbL;
            if (nb <= r) {
                const uint32_t bo = bOffN + nb * 16 * PIT * 2 + ks * 32;
                uint32_t kH[4], kL[4];
                ldsm4(sb + K3_KH + bo, kH);
                ldsm4(sb + K3_KL + bo, kL);
                mma16816(accP[2 * nbL],     qH, kH[0], kH[1]);
                mma16816(accP[2 * nbL + 1], qH, kH[2], kH[3]);
                mma16816(accP[2 * nbL],     qH, kL[0], kL[1]);
                mma16816(accP[2 * nbL + 1], qH, kL[2], kL[3]);
                mma16816(accP[2 * nbL],     qL, kH[0], kH[1]);
                mma16816(accP[2 * nbL + 1], qL, kH[2], kH[3]);
            }
        }
    }

    // ---- mask + split + store P quarter to dedicated smem P planes ----
#pragma unroll
    for (int nbL = 0; nbL < 2; nbL++) {
        const int nb = 2 * h + nbL;
        if (nb <= r) {
#pragma unroll
            for (int s2 = 0; s2 < 2; s2++) {
                const int j0 = 16 * nb + 8 * s2 + 2 * tig;
                float c0 = (j0     <= i0)     ? accP[2 * nbL + s2][0] : 0.f;
                float c1 = (j0 + 1 <= i0)     ? accP[2 * nbL + s2][1] : 0.f;
                float c2 = (j0     <= i0 + 8) ? accP[2 * nbL + s2][2] : 0.f;
                float c3 = (j0 + 1 <= i0 + 8) ? accP[2 * nbL + s2][3] : 0.f;
                uint32_t hw, lw;
                split2(c0, c1, hw, lw);
                *(uint32_t*)(sm + K3_PH + (i0 * PIT + j0) * 2) = hw;
                *(uint32_t*)(sm + K3_PL + (i0 * PIT + j0) * 2) = lw;
                split2(c2, c3, hw, lw);
                *(uint32_t*)(sm + K3_PH + ((i0 + 8) * PIT + j0) * 2) = hw;
                *(uint32_t*)(sm + K3_PL + ((i0 + 8) * PIT + j0) * 2) = lw;
            }
        }
    }
    __syncthreads();

    // ---- O1 = Q @ S (fused) for e-half h ----
    float accO[4][4] = {};
#pragma unroll
    for (int ks = 0; ks < 4; ks++) {
        uint32_t qH[4], qL[4];
        ldsm4(sb + K3_QH + aOffN + ks * 32, qH);
        ldsm4(sb + K3_QL + aOffN + ks * 32, qL);
#pragma unroll
        for (int nbL = 0; nbL < 2; nbL++) {
            const int nbE = 2 * h + nbL;
            const uint32_t bo = bOffT + ks * 16 * PIT * 2 + nbE * 32;
            uint32_t sH[4], sL[4];
            ldsm4t(sb + K3_SH + bo, sH);
            ldsm4t(sb + K3_SL + bo, sL);
            mma16816(accO[2 * nbL],     qH, sH[0], sH[1]);
            mma16816(accO[2 * nbL + 1], qH, sH[2], sH[3]);
            mma16816(accO[2 * nbL],     qH, sL[0], sL[1]);
            mma16816(accO[2 * nbL + 1], qH, sL[2], sL[3]);
            mma16816(accO[2 * nbL],     qL, sH[0], sH[1]);
            mma16816(accO[2 * nbL + 1], qL, sH[2], sH[3]);
        }
    }

    // ---- O2 += P @ V (fused; A = P from smem, kb <= r; B = V^T trans) ----
#pragma unroll
    for (int kb = 0; kb < 4; kb++)
        if (kb <= r) {
            uint32_t pH[4], pL[4];
            ldsm4(sb + K3_PH + aOffN + kb * 32, pH);
            ldsm4(sb + K3_PL + aOffN + kb * 32, pL);
#pragma unroll
            for (int nbL = 0; nbL < 2; nbL++) {
                const int nbE = 2 * h + nbL;
                const uint32_t bo = bOffT + kb * 16 * PIT * 2 + nbE * 32;
                uint32_t vH[4], vL[4];
                ldsm4t(sb + K3_VH + bo, vH);
                ldsm4t(sb + K3_VL + bo, vL);
                mma16816(accO[2 * nbL],     pH, vH[0], vH[1]);
                mma16816(accO[2 * nbL + 1], pH, vH[2], vH[3]);
                mma16816(accO[2 * nbL],     pH, vL[0], vL[1]);
                mma16816(accO[2 * nbL + 1], pH, vL[2], vL[3]);
                mma16816(accO[2 * nbL],     pL, vH[0], vH[1]);
                mma16816(accO[2 * nbL + 1], pL, vH[2], vH[3]);
            }
        }

    // ---- store O (rows i0, i0+8; cols 32h + 8*nb8 + 2*tig) ----
    float* op = og + ((size_t)bh * TT + (size_t)c * CH) * DD;
#pragma unroll
    for (int nb8 = 0; nb8 < 4; nb8++) {
        const int e = 32 * h + 8 * nb8 + 2 * tig;
        *(float2*)(op + (size_t)i0 * DD + e)       = make_float2(accO[nb8][0], accO[nb8][1]);
        *(float2*)(op + (size_t)(i0 + 8) * DD + e) = make_float2(accO[nb8][2], accO[nb8][3]);
    }
}

// ---------------------------------------------------------------------------
extern "C" void kernel_launch(void* const* d_in, const int* in_sizes, int n_in,
                              void* d_out, int out_size) {
    const float* q = (const float*)d_in[0];
    const float* k = (const float*)d_in[1];
    const float* v = (const float*)d_in[2];
    float* o = (float*)d_out;

    cudaFuncSetAttribute(kv_kernel, cudaFuncAttributeMaxDynamicSharedMemorySize, K1_SMEM);
    cudaFuncSetAttribute(out_kernel, cudaFuncAttributeMaxDynamicSharedMemorySize, K3_SMEM);

    dim3 grid(NC, BH);
    kv_kernel<<<grid, 256, K1_SMEM>>>(k, v);
    prefix_kernel<<<dim3((DD * DD) / 256, BH), 256>>>();
    out_kernel<<<grid, 256, K3_SMEM>>>(q, k, v, o);
}